// round 3
// baseline (speedup 1.0000x reference)
#include <cuda_runtime.h>

#define N_NODES 100000
#define N_EDGES 3200000
#define FIN 16
#define H 64

// ---------------- scratch (static __device__, no allocation) ----------------
__device__ __align__(16) float g_deg[N_NODES];
__device__ __align__(16) float g_dis[N_NODES];                 // deg^-1/2
__device__ __align__(16) float g_agg1[(size_t)N_NODES * FIN];  // 6.4 MB
__device__ __align__(16) float g_xw2[(size_t)N_NODES * H];     // 25.6 MB
__device__ __align__(16) float g_agg2[(size_t)N_NODES * H];    // 25.6 MB
__device__ int g_is_i64;   // 1 if edge_index is int64, 0 if int32

// Vectorized no-return global reduction (sm_90+): 16 B per op.
__device__ __forceinline__ void red_add_v4(float* addr, float4 v) {
    asm volatile("red.global.add.v4.f32 [%0], {%1,%2,%3,%4};"
                 :: "l"(addr), "f"(v.x), "f"(v.y), "f"(v.z), "f"(v.w)
                 : "memory");
}

// Read edge index #pos from buffer of unknown width (uniform branch on flag).
__device__ __forceinline__ int load_idx(const void* ei, size_t pos, int is64) {
    if (is64) return (int)((const long long*)ei)[pos];
    return ((const int*)ei)[pos];
}

// ---------------- kernels ----------------

// Detect int32 vs int64 edge_index. If the buffer is int64, every value is a
// node id < 2^31, so the high 32-bit word of each element is 0. Probe 32
// elements from the row half and 32 from the col half in parallel; if ANY
// high word is nonzero the data must be int32 (random ids, P[false pos]≈0).
__global__ void k_detect(const int* __restrict__ ei) {
    int lane = threadIdx.x;  // 0..31
    long long k1 = lane * 997;                       // spread over row half
    long long k2 = (long long)N_EDGES + lane * 997;  // spread over col half
    int nz = (ei[2 * k1 + 1] != 0) || (ei[2 * k2 + 1] != 0);
    unsigned any = __ballot_sync(0xFFFFFFFFu, nz);
    if (lane == 0) g_is_i64 = (any == 0u) ? 1 : 0;
}

// deg[i] = 1 (self-loop)
__global__ void k_deg_init() {
    int i = blockIdx.x * blockDim.x + threadIdx.x;
    if (i < N_NODES) g_deg[i] = 1.0f;
}

// deg[col[e]] += 1
__global__ void k_deg_count(const void* __restrict__ ei) {
    int e = blockIdx.x * blockDim.x + threadIdx.x;
    if (e >= N_EDGES) return;
    int is64 = g_is_i64;
    int c = load_idx(ei, (size_t)N_EDGES + e, is64);
    atomicAdd(&g_deg[c], 1.0f);
}

// dis = rsqrt(deg); agg1 init = self-loop message x[i] * (dis^2 = 1/deg)
__global__ void k_dis_agg1init(const float* __restrict__ x) {
    int i = blockIdx.x * blockDim.x + threadIdx.x;
    if (i >= N_NODES) return;
    float d = g_deg[i];               // >= 1 always (self-loop)
    g_dis[i] = rsqrtf(d);
    float inv = 1.0f / d;
    const float4* xr = (const float4*)(x + (size_t)i * FIN);
    float4* ar = (float4*)(g_agg1 + (size_t)i * FIN);
#pragma unroll
    for (int t = 0; t < 4; t++) {
        float4 v = xr[t];
        v.x *= inv; v.y *= inv; v.z *= inv; v.w *= inv;
        ar[t] = v;
    }
}

// Layer-1 aggregation in 16-dim x-space: agg1[col] += x[row] * dis[row]*dis[col]
__global__ void k_scatter1(const void* __restrict__ ei,
                           const float* __restrict__ x) {
    int e = blockIdx.x * blockDim.x + threadIdx.x;
    if (e >= N_EDGES) return;
    int is64 = g_is_i64;
    int r = load_idx(ei, (size_t)e, is64);
    int c = load_idx(ei, (size_t)N_EDGES + e, is64);
    float nrm = g_dis[r] * g_dis[c];
    const float4* src = (const float4*)(x + (size_t)r * FIN);
    float* dst = g_agg1 + (size_t)c * FIN;
#pragma unroll
    for (int t = 0; t < 4; t++) {
        float4 v = src[t];
        v.x *= nrm; v.y *= nrm; v.z *= nrm; v.w *= nrm;
        red_add_v4(dst + 4 * t, v);
    }
}

// Fused dense: h1 = relu(agg1 @ W1 + b1); xw2 = h1 @ W2;
// also write agg2 self-loop init = xw2 / deg.
__global__ void __launch_bounds__(128) k_dense(const float* __restrict__ W1,
                                               const float* __restrict__ b1,
                                               const float* __restrict__ W2) {
    __shared__ float sW1[FIN * H];   // 4 KB
    __shared__ float sW2[H * H];     // 16 KB
    __shared__ float sb1[H];
    int tid = threadIdx.x;
    for (int i = tid; i < FIN * H; i += blockDim.x) sW1[i] = W1[i];
    for (int i = tid; i < H * H; i += blockDim.x) sW2[i] = W2[i];
    for (int i = tid; i < H; i += blockDim.x) sb1[i] = b1[i];
    __syncthreads();

    int n = blockIdx.x * blockDim.x + tid;
    if (n >= N_NODES) return;

    float a[FIN];
    const float4* ag = (const float4*)(g_agg1 + (size_t)n * FIN);
#pragma unroll
    for (int t = 0; t < 4; t++) {
        float4 v = ag[t];
        a[4 * t + 0] = v.x; a[4 * t + 1] = v.y;
        a[4 * t + 2] = v.z; a[4 * t + 3] = v.w;
    }

    float h1r[H];
#pragma unroll
    for (int jb = 0; jb < H; jb += 4) {
        float4 acc = *(const float4*)&sb1[jb];
#pragma unroll
        for (int f = 0; f < FIN; f++) {
            float4 w = *(const float4*)&sW1[f * H + jb];  // uniform -> broadcast
            acc.x += a[f] * w.x; acc.y += a[f] * w.y;
            acc.z += a[f] * w.z; acc.w += a[f] * w.w;
        }
        h1r[jb + 0] = fmaxf(acc.x, 0.0f);
        h1r[jb + 1] = fmaxf(acc.y, 0.0f);
        h1r[jb + 2] = fmaxf(acc.z, 0.0f);
        h1r[jb + 3] = fmaxf(acc.w, 0.0f);
    }

    float di = g_dis[n];
    float invd = di * di;   // 1/deg = self-loop norm
    float4* oxw = (float4*)(g_xw2 + (size_t)n * H);
    float4* oag = (float4*)(g_agg2 + (size_t)n * H);
#pragma unroll 1
    for (int jb = 0; jb < H; jb += 4) {
        float4 acc = make_float4(0.f, 0.f, 0.f, 0.f);
#pragma unroll
        for (int k = 0; k < H; k++) {
            float4 w = *(const float4*)&sW2[k * H + jb];  // uniform -> broadcast
            float hk = h1r[k];
            acc.x += hk * w.x; acc.y += hk * w.y;
            acc.z += hk * w.z; acc.w += hk * w.w;
        }
        oxw[jb / 4] = acc;
        float4 s = acc;
        s.x *= invd; s.y *= invd; s.z *= invd; s.w *= invd;
        oag[jb / 4] = s;
    }
}

// Layer-2 aggregation (64-dim): agg2[col] += xw2[row] * dis[row]*dis[col]
__global__ void k_scatter2(const void* __restrict__ ei) {
    int e = blockIdx.x * blockDim.x + threadIdx.x;
    if (e >= N_EDGES) return;
    int is64 = g_is_i64;
    int r = load_idx(ei, (size_t)e, is64);
    int c = load_idx(ei, (size_t)N_EDGES + e, is64);
    float nrm = g_dis[r] * g_dis[c];
    const float4* src = (const float4*)(g_xw2 + (size_t)r * H);
    float* dst = g_agg2 + (size_t)c * H;
#pragma unroll
    for (int t = 0; t < 16; t++) {
        float4 v = src[t];
        v.x *= nrm; v.y *= nrm; v.z *= nrm; v.w *= nrm;
        red_add_v4(dst + 4 * t, v);
    }
}

// h2 = relu(agg2 + b2); out = sigmoid(h2 @ Wf + bf)
__global__ void k_final(const float* __restrict__ b2,
                        const float* __restrict__ Wf,
                        const float* __restrict__ bf,
                        float* __restrict__ out) {
    __shared__ float sb2[H];
    __shared__ float sWf[H];
    int tid = threadIdx.x;
    if (tid < H) { sb2[tid] = b2[tid]; sWf[tid] = Wf[tid]; }
    __syncthreads();
    int n = blockIdx.x * blockDim.x + tid;
    if (n >= N_NODES) return;
    const float4* ag = (const float4*)(g_agg2 + (size_t)n * H);
    float s = bf[0];
#pragma unroll
    for (int t = 0; t < 16; t++) {
        float4 v = ag[t];
        s += fmaxf(v.x + sb2[4 * t + 0], 0.0f) * sWf[4 * t + 0];
        s += fmaxf(v.y + sb2[4 * t + 1], 0.0f) * sWf[4 * t + 1];
        s += fmaxf(v.z + sb2[4 * t + 2], 0.0f) * sWf[4 * t + 2];
        s += fmaxf(v.w + sb2[4 * t + 3], 0.0f) * sWf[4 * t + 3];
    }
    out[n] = 1.0f / (1.0f + expf(-s));
}

// ---------------- launch ----------------
extern "C" void kernel_launch(void* const* d_in, const int* in_sizes, int n_in,
                              void* d_out, int out_size) {
    const float* x  = (const float*)d_in[0];
    const void*  ei = d_in[1];                 // [2, E] int32 OR int64
    const float* W1 = (const float*)d_in[2];
    const float* b1 = (const float*)d_in[3];
    const float* W2 = (const float*)d_in[4];
    const float* b2 = (const float*)d_in[5];
    const float* Wf = (const float*)d_in[6];
    const float* bf = (const float*)d_in[7];
    float* out = (float*)d_out;

    const int TB = 256;
    k_detect      <<<1, 32>>>((const int*)ei);
    k_deg_init    <<<(N_NODES + TB - 1) / TB, TB>>>();
    k_deg_count   <<<(N_EDGES + TB - 1) / TB, TB>>>(ei);
    k_dis_agg1init<<<(N_NODES + TB - 1) / TB, TB>>>(x);
    k_scatter1    <<<(N_EDGES + TB - 1) / TB, TB>>>(ei, x);
    k_dense       <<<(N_NODES + 127) / 128, 128>>>(W1, b1, W2);
    k_scatter2    <<<(N_EDGES + TB - 1) / TB, TB>>>(ei);
    k_final       <<<(N_NODES + TB - 1) / TB, TB>>>(b2, Wf, bf, out);
}

// round 4
// speedup vs baseline: 1.8507x; 1.8507x over previous
#include <cuda_runtime.h>

#define N_NODES 100000
#define N_EDGES 3200000
#define FIN 16
#define H 64

// ---------------- scratch (static __device__, no allocation) ----------------
__device__ __align__(16) float g_deg[N_NODES];
__device__ __align__(16) float g_dis[N_NODES];                 // deg^-1/2
__device__ __align__(16) float g_agg1[(size_t)N_NODES * FIN];  // 6.4 MB
__device__ __align__(16) float g_xw2[(size_t)N_NODES * H];     // 25.6 MB
__device__ __align__(16) float g_agg2[(size_t)N_NODES * H];    // 25.6 MB
__device__ __align__(16) int2  g_eidx[N_EDGES];                // packed (row,col) 25.6 MB
__device__ __align__(16) float g_enrm[N_EDGES];                // dis[r]*dis[c]   12.8 MB
__device__ int g_is_i64;   // 1 if edge_index is int64, 0 if int32

// Vectorized no-return global reduction (sm_90+): 16 B per op.
__device__ __forceinline__ void red_add_v4(float* addr, float4 v) {
    asm volatile("red.global.add.v4.f32 [%0], {%1,%2,%3,%4};"
                 :: "l"(addr), "f"(v.x), "f"(v.y), "f"(v.z), "f"(v.w)
                 : "memory");
}

__device__ __forceinline__ int load_idx(const void* ei, size_t pos, int is64) {
    if (is64) return (int)((const long long*)ei)[pos];
    return ((const int*)ei)[pos];
}

// ---------------- kernels ----------------

// Detect int32 vs int64 edge_index: int64 node ids < 2^31 -> high words all 0.
__global__ void k_detect(const int* __restrict__ ei) {
    int lane = threadIdx.x;  // 0..31
    long long k1 = lane * 997;
    long long k2 = (long long)N_EDGES + lane * 997;
    int nz = (ei[2 * k1 + 1] != 0) || (ei[2 * k2 + 1] != 0);
    unsigned any = __ballot_sync(0xFFFFFFFFu, nz);
    if (lane == 0) g_is_i64 = (any == 0u) ? 1 : 0;
}

// deg[i] = 1 (self-loop)
__global__ void k_deg_init() {
    int i = blockIdx.x * blockDim.x + threadIdx.x;
    if (i < N_NODES) g_deg[i] = 1.0f;
}

// deg[col[e]] += 1
__global__ void k_deg_count(const void* __restrict__ ei) {
    int e = blockIdx.x * blockDim.x + threadIdx.x;
    if (e >= N_EDGES) return;
    int c = load_idx(ei, (size_t)N_EDGES + e, g_is_i64);
    atomicAdd(&g_deg[c], 1.0f);
}

// dis = rsqrt(deg); agg1 init = self-loop message x[i] / deg
__global__ void k_dis_agg1init(const float* __restrict__ x) {
    int i = blockIdx.x * blockDim.x + threadIdx.x;
    if (i >= N_NODES) return;
    float d = g_deg[i];
    g_dis[i] = rsqrtf(d);
    float inv = 1.0f / d;
    const float4* xr = (const float4*)(x + (size_t)i * FIN);
    float4* ar = (float4*)(g_agg1 + (size_t)i * FIN);
#pragma unroll
    for (int t = 0; t < 4; t++) {
        float4 v = xr[t];
        v.x *= inv; v.y *= inv; v.z *= inv; v.w *= inv;
        ar[t] = v;
    }
}

// Per-edge metadata: decode indices once, compute norm once.
__global__ void k_prep(const void* __restrict__ ei) {
    int e = blockIdx.x * blockDim.x + threadIdx.x;
    if (e >= N_EDGES) return;
    int is64 = g_is_i64;
    int r = load_idx(ei, (size_t)e, is64);
    int c = load_idx(ei, (size_t)N_EDGES + e, is64);
    g_eidx[e] = make_int2(r, c);
    g_enrm[e] = g_dis[r] * g_dis[c];
}

// Layer-1 aggregation in 16-dim x-space. 4 threads per edge, one float4 each:
// lanes of one edge hit the same 128B line -> coalesced gather + RED.
__global__ void k_scatter1(const float* __restrict__ x) {
    unsigned gid = blockIdx.x * blockDim.x + threadIdx.x;
    unsigned e = gid >> 2;
    if (e >= N_EDGES) return;
    int k = gid & 3;
    int2 rc = g_eidx[e];        // broadcast within the 4-lane group
    float nrm = g_enrm[e];
    float4 v = *(const float4*)(x + (size_t)rc.x * FIN + 4 * k);
    v.x *= nrm; v.y *= nrm; v.z *= nrm; v.w *= nrm;
    red_add_v4(g_agg1 + (size_t)rc.y * FIN + 4 * k, v);
}

// Fused dense: h1 = relu(agg1 @ W1 + b1); xw2 = h1 @ W2;
// also write agg2 self-loop init = xw2 / deg.
__global__ void __launch_bounds__(128) k_dense(const float* __restrict__ W1,
                                               const float* __restrict__ b1,
                                               const float* __restrict__ W2) {
    __shared__ float sW1[FIN * H];   // 4 KB
    __shared__ float sW2[H * H];     // 16 KB
    __shared__ float sb1[H];
    int tid = threadIdx.x;
    for (int i = tid; i < FIN * H; i += blockDim.x) sW1[i] = W1[i];
    for (int i = tid; i < H * H; i += blockDim.x) sW2[i] = W2[i];
    for (int i = tid; i < H; i += blockDim.x) sb1[i] = b1[i];
    __syncthreads();

    int n = blockIdx.x * blockDim.x + tid;
    if (n >= N_NODES) return;

    float a[FIN];
    const float4* ag = (const float4*)(g_agg1 + (size_t)n * FIN);
#pragma unroll
    for (int t = 0; t < 4; t++) {
        float4 v = ag[t];
        a[4 * t + 0] = v.x; a[4 * t + 1] = v.y;
        a[4 * t + 2] = v.z; a[4 * t + 3] = v.w;
    }

    float h1r[H];
#pragma unroll
    for (int jb = 0; jb < H; jb += 4) {
        float4 acc = *(const float4*)&sb1[jb];
#pragma unroll
        for (int f = 0; f < FIN; f++) {
            float4 w = *(const float4*)&sW1[f * H + jb];  // uniform -> broadcast
            acc.x += a[f] * w.x; acc.y += a[f] * w.y;
            acc.z += a[f] * w.z; acc.w += a[f] * w.w;
        }
        h1r[jb + 0] = fmaxf(acc.x, 0.0f);
        h1r[jb + 1] = fmaxf(acc.y, 0.0f);
        h1r[jb + 2] = fmaxf(acc.z, 0.0f);
        h1r[jb + 3] = fmaxf(acc.w, 0.0f);
    }

    float di = g_dis[n];
    float invd = di * di;   // 1/deg = self-loop norm
    float4* oxw = (float4*)(g_xw2 + (size_t)n * H);
    float4* oag = (float4*)(g_agg2 + (size_t)n * H);
#pragma unroll 1
    for (int jb = 0; jb < H; jb += 4) {
        float4 acc = make_float4(0.f, 0.f, 0.f, 0.f);
#pragma unroll
        for (int k = 0; k < H; k++) {
            float4 w = *(const float4*)&sW2[k * H + jb];  // uniform -> broadcast
            float hk = h1r[k];
            acc.x += hk * w.x; acc.y += hk * w.y;
            acc.z += hk * w.z; acc.w += hk * w.w;
        }
        oxw[jb / 4] = acc;
        float4 s = acc;
        s.x *= invd; s.y *= invd; s.z *= invd; s.w *= invd;
        oag[jb / 4] = s;
    }
}

// Layer-2 aggregation (64-dim). 16 threads per edge, one float4 each:
// a warp covers 2 edges; gather/RED touch ~2 lines per row -> coalesced.
__global__ void k_scatter2() {
    unsigned gid = blockIdx.x * blockDim.x + threadIdx.x;
    unsigned e = gid >> 4;
    if (e >= N_EDGES) return;
    int k = gid & 15;
    int2 rc = g_eidx[e];        // broadcast within the 16-lane group
    float nrm = g_enrm[e];
    float4 v = *(const float4*)(g_xw2 + (size_t)rc.x * H + 4 * k);
    v.x *= nrm; v.y *= nrm; v.z *= nrm; v.w *= nrm;
    red_add_v4(g_agg2 + (size_t)rc.y * H + 4 * k, v);
}

// h2 = relu(agg2 + b2); out = sigmoid(h2 @ Wf + bf)
__global__ void k_final(const float* __restrict__ b2,
                        const float* __restrict__ Wf,
                        const float* __restrict__ bf,
                        float* __restrict__ out) {
    __shared__ float sb2[H];
    __shared__ float sWf[H];
    int tid = threadIdx.x;
    if (tid < H) { sb2[tid] = b2[tid]; sWf[tid] = Wf[tid]; }
    __syncthreads();
    int n = blockIdx.x * blockDim.x + tid;
    if (n >= N_NODES) return;
    const float4* ag = (const float4*)(g_agg2 + (size_t)n * H);
    float s = bf[0];
#pragma unroll
    for (int t = 0; t < 16; t++) {
        float4 v = ag[t];
        s += fmaxf(v.x + sb2[4 * t + 0], 0.0f) * sWf[4 * t + 0];
        s += fmaxf(v.y + sb2[4 * t + 1], 0.0f) * sWf[4 * t + 1];
        s += fmaxf(v.z + sb2[4 * t + 2], 0.0f) * sWf[4 * t + 2];
        s += fmaxf(v.w + sb2[4 * t + 3], 0.0f) * sWf[4 * t + 3];
    }
    out[n] = 1.0f / (1.0f + expf(-s));
}

// ---------------- launch ----------------
extern "C" void kernel_launch(void* const* d_in, const int* in_sizes, int n_in,
                              void* d_out, int out_size) {
    const float* x  = (const float*)d_in[0];
    const void*  ei = d_in[1];                 // [2, E] int32 OR int64
    const float* W1 = (const float*)d_in[2];
    const float* b1 = (const float*)d_in[3];
    const float* W2 = (const float*)d_in[4];
    const float* b2 = (const float*)d_in[5];
    const float* Wf = (const float*)d_in[6];
    const float* bf = (const float*)d_in[7];
    float* out = (float*)d_out;

    const int TB = 256;
    k_detect      <<<1, 32>>>((const int*)ei);
    k_deg_init    <<<(N_NODES + TB - 1) / TB, TB>>>();
    k_deg_count   <<<(N_EDGES + TB - 1) / TB, TB>>>(ei);
    k_dis_agg1init<<<(N_NODES + TB - 1) / TB, TB>>>(x);
    k_prep        <<<(N_EDGES + TB - 1) / TB, TB>>>(ei);
    k_scatter1    <<<((size_t)N_EDGES * 4 + TB - 1) / TB, TB>>>(x);
    k_dense       <<<(N_NODES + 127) / 128, 128>>>(W1, b1, W2);
    k_scatter2    <<<((size_t)N_EDGES * 16 + TB - 1) / TB, TB>>>();
    k_final       <<<(N_NODES + TB - 1) / TB, TB>>>(b2, Wf, bf, out);
}

// round 5
// speedup vs baseline: 1.8536x; 1.0016x over previous
#include <cuda_runtime.h>

#define N_NODES 100000
#define N_EDGES 3200000
#define FIN 16
#define H 64

// ---------------- scratch (static __device__, no allocation) ----------------
__device__ __align__(16) float g_deg[N_NODES];
__device__ __align__(16) float g_dis[N_NODES];                 // deg^-1/2
__device__ __align__(16) float g_agg1[(size_t)N_NODES * FIN];  // 6.4 MB
__device__ __align__(16) float g_xw2[(size_t)N_NODES * H];     // 25.6 MB
__device__ __align__(16) float g_agg2[(size_t)N_NODES * H];    // 25.6 MB
__device__ __align__(16) int2  g_eidx[N_EDGES];                // packed (row,col) 25.6 MB
__device__ __align__(16) float g_enrm[N_EDGES];                // dis[r]*dis[c]   12.8 MB
__device__ int g_is_i64;   // 1 if edge_index is int64, 0 if int32

// Vectorized no-return global reduction (sm_90+): 16 B per op.
__device__ __forceinline__ void red_add_v4(float* addr, float4 v) {
    asm volatile("red.global.add.v4.f32 [%0], {%1,%2,%3,%4};"
                 :: "l"(addr), "f"(v.x), "f"(v.y), "f"(v.z), "f"(v.w)
                 : "memory");
}

__device__ __forceinline__ int load_idx(const void* ei, size_t pos, int is64) {
    if (is64) return (int)((const long long*)ei)[pos];
    return ((const int*)ei)[pos];
}

// ---------------- kernels ----------------

// Detect int32 vs int64 edge_index: int64 node ids < 2^31 -> high words all 0.
__global__ void k_detect(const int* __restrict__ ei) {
    int lane = threadIdx.x;  // 0..31
    long long k1 = lane * 997;
    long long k2 = (long long)N_EDGES + lane * 997;
    int nz = (ei[2 * k1 + 1] != 0) || (ei[2 * k2 + 1] != 0);
    unsigned any = __ballot_sync(0xFFFFFFFFu, nz);
    if (lane == 0) g_is_i64 = (any == 0u) ? 1 : 0;
}

// deg[i] = 1 (self-loop)
__global__ void k_deg_init() {
    int i = blockIdx.x * blockDim.x + threadIdx.x;
    if (i < N_NODES) g_deg[i] = 1.0f;
}

// deg[col[e]] += 1
__global__ void k_deg_count(const void* __restrict__ ei) {
    int e = blockIdx.x * blockDim.x + threadIdx.x;
    if (e >= N_EDGES) return;
    int c = load_idx(ei, (size_t)N_EDGES + e, g_is_i64);
    atomicAdd(&g_deg[c], 1.0f);
}

// dis = rsqrt(deg); agg1 init = self-loop message x[i] / deg
__global__ void k_dis_agg1init(const float* __restrict__ x) {
    int i = blockIdx.x * blockDim.x + threadIdx.x;
    if (i >= N_NODES) return;
    float d = g_deg[i];
    g_dis[i] = rsqrtf(d);
    float inv = 1.0f / d;
    const float4* xr = (const float4*)(x + (size_t)i * FIN);
    float4* ar = (float4*)(g_agg1 + (size_t)i * FIN);
#pragma unroll
    for (int t = 0; t < 4; t++) {
        float4 v = xr[t];
        v.x *= inv; v.y *= inv; v.z *= inv; v.w *= inv;
        ar[t] = v;
    }
}

// Per-edge metadata: decode indices once, compute norm once.
__global__ void k_prep(const void* __restrict__ ei) {
    int e = blockIdx.x * blockDim.x + threadIdx.x;
    if (e >= N_EDGES) return;
    int is64 = g_is_i64;
    int r = load_idx(ei, (size_t)e, is64);
    int c = load_idx(ei, (size_t)N_EDGES + e, is64);
    g_eidx[e] = make_int2(r, c);
    g_enrm[e] = g_dis[r] * g_dis[c];
}

// Layer-1 aggregation in 16-dim x-space. 4 threads per edge, one float4 each:
// lanes of one edge hit the same 128B line -> coalesced gather + RED.
__global__ void k_scatter1(const float* __restrict__ x) {
    unsigned gid = blockIdx.x * blockDim.x + threadIdx.x;
    unsigned e = gid >> 2;
    if (e >= N_EDGES) return;
    int k = gid & 3;
    int2 rc = g_eidx[e];        // broadcast within the 4-lane group
    float nrm = g_enrm[e];
    float4 v = *(const float4*)(x + (size_t)rc.x * FIN + 4 * k);
    v.x *= nrm; v.y *= nrm; v.z *= nrm; v.w *= nrm;
    red_add_v4(g_agg1 + (size_t)rc.y * FIN + 4 * k, v);
}

// Fused dense: h1 = relu(agg1 @ W1 + b1); xw2 = h1 @ W2;
// also write agg2 self-loop init = xw2 / deg.
__global__ void __launch_bounds__(128) k_dense(const float* __restrict__ W1,
                                               const float* __restrict__ b1,
                                               const float* __restrict__ W2) {
    __shared__ float sW1[FIN * H];   // 4 KB
    __shared__ float sW2[H * H];     // 16 KB
    __shared__ float sb1[H];
    int tid = threadIdx.x;
    for (int i = tid; i < FIN * H; i += blockDim.x) sW1[i] = W1[i];
    for (int i = tid; i < H * H; i += blockDim.x) sW2[i] = W2[i];
    for (int i = tid; i < H; i += blockDim.x) sb1[i] = b1[i];
    __syncthreads();

    int n = blockIdx.x * blockDim.x + tid;
    if (n >= N_NODES) return;

    float a[FIN];
    const float4* ag = (const float4*)(g_agg1 + (size_t)n * FIN);
#pragma unroll
    for (int t = 0; t < 4; t++) {
        float4 v = ag[t];
        a[4 * t + 0] = v.x; a[4 * t + 1] = v.y;
        a[4 * t + 2] = v.z; a[4 * t + 3] = v.w;
    }

    float h1r[H];
#pragma unroll
    for (int jb = 0; jb < H; jb += 4) {
        float4 acc = *(const float4*)&sb1[jb];
#pragma unroll
        for (int f = 0; f < FIN; f++) {
            float4 w = *(const float4*)&sW1[f * H + jb];  // uniform -> broadcast
            acc.x += a[f] * w.x; acc.y += a[f] * w.y;
            acc.z += a[f] * w.z; acc.w += a[f] * w.w;
        }
        h1r[jb + 0] = fmaxf(acc.x, 0.0f);
        h1r[jb + 1] = fmaxf(acc.y, 0.0f);
        h1r[jb + 2] = fmaxf(acc.z, 0.0f);
        h1r[jb + 3] = fmaxf(acc.w, 0.0f);
    }

    float di = g_dis[n];
    float invd = di * di;   // 1/deg = self-loop norm
    float4* oxw = (float4*)(g_xw2 + (size_t)n * H);
    float4* oag = (float4*)(g_agg2 + (size_t)n * H);
#pragma unroll 1
    for (int jb = 0; jb < H; jb += 4) {
        float4 acc = make_float4(0.f, 0.f, 0.f, 0.f);
#pragma unroll
        for (int k = 0; k < H; k++) {
            float4 w = *(const float4*)&sW2[k * H + jb];  // uniform -> broadcast
            float hk = h1r[k];
            acc.x += hk * w.x; acc.y += hk * w.y;
            acc.z += hk * w.z; acc.w += hk * w.w;
        }
        oxw[jb / 4] = acc;
        float4 s = acc;
        s.x *= invd; s.y *= invd; s.z *= invd; s.w *= invd;
        oag[jb / 4] = s;
    }
}

// Layer-2 aggregation (64-dim). 16 threads per edge, one float4 each:
// a warp covers 2 edges; gather/RED touch ~2 lines per row -> coalesced.
__global__ void k_scatter2() {
    unsigned gid = blockIdx.x * blockDim.x + threadIdx.x;
    unsigned e = gid >> 4;
    if (e >= N_EDGES) return;
    int k = gid & 15;
    int2 rc = g_eidx[e];        // broadcast within the 16-lane group
    float nrm = g_enrm[e];
    float4 v = *(const float4*)(g_xw2 + (size_t)rc.x * H + 4 * k);
    v.x *= nrm; v.y *= nrm; v.z *= nrm; v.w *= nrm;
    red_add_v4(g_agg2 + (size_t)rc.y * H + 4 * k, v);
}

// h2 = relu(agg2 + b2); out = sigmoid(h2 @ Wf + bf)
__global__ void k_final(const float* __restrict__ b2,
                        const float* __restrict__ Wf,
                        const float* __restrict__ bf,
                        float* __restrict__ out) {
    __shared__ float sb2[H];
    __shared__ float sWf[H];
    int tid = threadIdx.x;
    if (tid < H) { sb2[tid] = b2[tid]; sWf[tid] = Wf[tid]; }
    __syncthreads();
    int n = blockIdx.x * blockDim.x + tid;
    if (n >= N_NODES) return;
    const float4* ag = (const float4*)(g_agg2 + (size_t)n * H);
    float s = bf[0];
#pragma unroll
    for (int t = 0; t < 16; t++) {
        float4 v = ag[t];
        s += fmaxf(v.x + sb2[4 * t + 0], 0.0f) * sWf[4 * t + 0];
        s += fmaxf(v.y + sb2[4 * t + 1], 0.0f) * sWf[4 * t + 1];
        s += fmaxf(v.z + sb2[4 * t + 2], 0.0f) * sWf[4 * t + 2];
        s += fmaxf(v.w + sb2[4 * t + 3], 0.0f) * sWf[4 * t + 3];
    }
    out[n] = 1.0f / (1.0f + expf(-s));
}

// ---------------- launch ----------------
extern "C" void kernel_launch(void* const* d_in, const int* in_sizes, int n_in,
                              void* d_out, int out_size) {
    const float* x  = (const float*)d_in[0];
    const void*  ei = d_in[1];                 // [2, E] int32 OR int64
    const float* W1 = (const float*)d_in[2];
    const float* b1 = (const float*)d_in[3];
    const float* W2 = (const float*)d_in[4];
    const float* b2 = (const float*)d_in[5];
    const float* Wf = (const float*)d_in[6];
    const float* bf = (const float*)d_in[7];
    float* out = (float*)d_out;

    const int TB = 256;
    k_detect      <<<1, 32>>>((const int*)ei);
    k_deg_init    <<<(N_NODES + TB - 1) / TB, TB>>>();
    k_deg_count   <<<(N_EDGES + TB - 1) / TB, TB>>>(ei);
    k_dis_agg1init<<<(N_NODES + TB - 1) / TB, TB>>>(x);
    k_prep        <<<(N_EDGES + TB - 1) / TB, TB>>>(ei);
    k_scatter1    <<<((size_t)N_EDGES * 4 + TB - 1) / TB, TB>>>(x);
    k_dense       <<<(N_NODES + 127) / 128, 128>>>(W1, b1, W2);
    k_scatter2    <<<((size_t)N_EDGES * 16 + TB - 1) / TB, TB>>>();
    k_final       <<<(N_NODES + TB - 1) / TB, TB>>>(b2, Wf, bf, out);
}